// round 2
// baseline (speedup 1.0000x reference)
#include <cuda_runtime.h>
#include <math.h>
#include <math_constants.h>

#define NPIX  32768      // 128*256 pixels
#define NE    128
#define NS    2048
#define NTOT  (16*128*2048)
#define CNT   4194304.0  // per-channel BN count = NPIX*NE

// ---------------- scratch ----------------
__device__ float    g_act0[NPIX * 2 * NE];
__device__ float    g_actA[NPIX * 8 * NE];
__device__ float    g_actB[NPIX * 8 * NE];
__device__ float    g_wraw[NPIX * NE];
__device__ float    g_sumI[NPIX];
__device__ float    g_sumQ[NPIX];
__device__ float    g_ydb [NPIX];
__device__ unsigned g_maxsq;
__device__ unsigned g_maxydb;
__device__ double   g_stats[4][16];   // per-layer [sum(8) | sumsq(8)]

__device__ __forceinline__ unsigned ford(float f) {
    unsigned u = __float_as_uint(f);
    return (u & 0x80000000u) ? ~u : (u | 0x80000000u);
}

__global__ void k_init() {
    int t = threadIdx.x;
    if (t < 64) ((double*)g_stats)[t] = 0.0;
    if (t == 64) g_maxsq = 0u;
    if (t == 65) g_maxydb = 0u;
}

__global__ void k_nrm(const float* __restrict__ id, const float* __restrict__ qd) {
    float m = 0.f;
    for (int i = blockIdx.x * blockDim.x + threadIdx.x; i < NTOT; i += gridDim.x * blockDim.x) {
        float a = id[i], b = qd[i];
        m = fmaxf(m, a * a + b * b);
    }
    for (int off = 16; off; off >>= 1) m = fmaxf(m, __shfl_down_sync(0xffffffffu, m, off));
    __shared__ float sm[8];
    int lane = threadIdx.x & 31, w = threadIdx.x >> 5;
    if (lane == 0) sm[w] = m;
    __syncthreads();
    if (threadIdx.x == 0) {
        float mm = sm[0];
        for (int i = 1; i < (int)(blockDim.x >> 5); i++) mm = fmaxf(mm, sm[i]);
        atomicMax(&g_maxsq, __float_as_uint(mm));
    }
}

__global__ void k_bf(const float* __restrict__ idata, const float* __restrict__ qdata,
                     const float* __restrict__ angles, const float* __restrict__ ele_pos,
                     const float* __restrict__ time_zero, const float* __restrict__ grid) {
    int p = blockIdx.x;
    int e = threadIdx.x;
    float x = grid[p * 3 + 0];
    float z = grid[p * 3 + 2];
    float ang = angles[0];
    float sA, cA;
    sincosf(ang, &sA, &cA);
    float ex  = ele_pos[e * 3];
    float ex0 = ele_pos[0];
    float exL = ele_pos[(NE - 1) * 3];

    const float FSC = (float)(20832000.0 / 1540.0);
    float txdel = (x * sA + z * cA + time_zero[0] * 1540.0f) * FSC;
    float vx = x - ex;
    float dist = sqrtf(vx * vx + z * z);
    float delays = txdel + dist * FSC;
    float d0 = floorf(delays);
    float frac = delays - d0;
    int i0 = (int)d0;

    const float* is = idata + e * NS;
    const float* qs = qdata + e * NS;
    float iv0 = (i0 >= 0 && i0 < NS)         ? is[i0]     : 0.f;
    float iv1 = (i0 + 1 >= 0 && i0 + 1 < NS) ? is[i0 + 1] : 0.f;
    float qv0 = (i0 >= 0 && i0 < NS)         ? qs[i0]     : 0.f;
    float qv1 = (i0 + 1 >= 0 && i0 + 1 < NS) ? qs[i0 + 1] : 0.f;

    float invn = rsqrtf(__uint_as_float(g_maxsq));
    float ifoc = (iv0 * (1.f - frac) + iv1 * frac) * invn;
    float qfoc = (qv0 * (1.f - frac) + qv1 * frac) * invn;

    float tshift = delays / 20832000.0f - (z * 2.0f) / 1540.0f;
    float theta = (float)(2.0 * CUDART_PI * 5208000.0) * tshift;
    float st, ct;
    sincosf(theta, &st, &ct);
    float ir = ifoc * ct - qfoc * st;
    float qr = qfoc * ct + ifoc * st;

    float avx = fabsf(vx);
    bool mrx = (fabsf(z) > avx) || (avx <= 0.001f) ||
               ((vx >= 0.001f)  && (x <= ex0)) ||
               ((vx <= -0.001f) && (x >= exL));
    float xp = x - z * tanf(ang);
    bool mtx = (xp >= ex0 * 1.2f) && (xp <= exL * 1.2f);
    if (!(mrx && mtx)) { ir = 0.f; qr = 0.f; }

    g_act0[p * 256 + e]       = ir;
    g_act0[p * 256 + 128 + e] = qr;

    float si = ir, sq = qr;
    for (int off = 16; off; off >>= 1) {
        si += __shfl_down_sync(0xffffffffu, si, off);
        sq += __shfl_down_sync(0xffffffffu, sq, off);
    }
    __shared__ float sI[4], sQ[4];
    int lane = e & 31, w = e >> 5;
    if (lane == 0) { sI[w] = si; sQ[w] = sq; }
    __syncthreads();
    if (e == 0) {
        g_sumI[p] = sI[0] + sI[1] + sI[2] + sI[3];
        g_sumQ[p] = sQ[0] + sQ[1] + sQ[2] + sQ[3];
    }
}

// ---- conv1: 2->8, K=65, pad=32. One thread per (pixel,e), all 8 out channels. ----
__global__ void __launch_bounds__(512) k_conv1(const float* __restrict__ w,
                                               const float* __restrict__ b) {
    __shared__ float sw[1040];
    __shared__ float sx[4][2][192];
    __shared__ float sred[16];
    int tid = threadIdx.x;
    int pbase = blockIdx.x * 4;

    for (int i = tid; i < 1040; i += 512) sw[i] = w[i];
    if (tid < 16) sred[tid] = 0.f;
    for (int i = tid; i < 4 * 2 * 192; i += 512) {
        int lp = i / 384, r = i % 384, c = r / 192, xi = r % 192;
        int e = xi - 32;
        sx[lp][c][xi] = (e >= 0 && e < 128) ? g_act0[(pbase + lp) * 256 + c * 128 + e] : 0.f;
    }
    __syncthreads();

    int lp = tid >> 7, e = tid & 127;
    float acc[8];
#pragma unroll
    for (int co = 0; co < 8; co++) acc[co] = b[co];

#pragma unroll
    for (int ci = 0; ci < 2; ci++) {
        const float* xp = &sx[lp][ci][e];
#pragma unroll
        for (int kb = 0; kb < 65; kb += 13) {
            float xw[13];
#pragma unroll
            for (int k = 0; k < 13; k++) xw[k] = xp[kb + k];
#pragma unroll
            for (int k = 0; k < 13; k++)
#pragma unroll
                for (int co = 0; co < 8; co++)
                    acc[co] = fmaf(sw[(co * 2 + ci) * 65 + kb + k], xw[k], acc[co]);
        }
    }

    int p = pbase + lp;
#pragma unroll
    for (int co = 0; co < 8; co++) g_actA[p * 1024 + co * 128 + e] = acc[co];

    int lane = tid & 31;
#pragma unroll
    for (int co = 0; co < 8; co++) {
        float s = acc[co], ss = acc[co] * acc[co];
        for (int off = 16; off; off >>= 1) {
            s  += __shfl_down_sync(0xffffffffu, s,  off);
            ss += __shfl_down_sync(0xffffffffu, ss, off);
        }
        if (lane == 0) { atomicAdd(&sred[co], s); atomicAdd(&sred[8 + co], ss); }
    }
    __syncthreads();
    if (tid < 8) {
        atomicAdd(&g_stats[0][tid],     (double)sred[tid]);
        atomicAdd(&g_stats[0][8 + tid], (double)sred[8 + tid]);
    }
}

// ---- conv2/3: BN(prev layer params!)+relu fused on load; 8->8, K=15, pad=7 ----
__global__ void __launch_bounds__(512) k_conv23(const float* __restrict__ w,
                                                const float* __restrict__ b,
                                                const float* __restrict__ gam,
                                                const float* __restrict__ bet,
                                                int layer, int flip) {
    __shared__ float sw[960];
    __shared__ float ssc[8], ssh[8];
    __shared__ float sx[4][8][142];
    __shared__ float sred[16];
    const float* in  = flip ? g_actB : g_actA;
    float*       out = flip ? g_actA : g_actB;

    int tid = threadIdx.x;
    int pbase = blockIdx.x * 4;

    for (int i = tid; i < 960; i += 512) sw[i] = w[i];
    if (tid < 8) {
        double mu  = g_stats[layer - 1][tid] / CNT;
        double var = g_stats[layer - 1][8 + tid] / CNT - mu * mu;
        float sc = (float)((double)gam[tid] / sqrt(var + 1e-5));
        ssc[tid] = sc;
        ssh[tid] = bet[tid] - (float)mu * sc;
    }
    if (tid < 16) sred[tid] = 0.f;
    __syncthreads();

    for (int i = tid; i < 4 * 8 * 142; i += 512) {
        int lp = i / 1136, r = i % 1136, c = r / 142, xi = r % 142;
        int e = xi - 7;
        float v = 0.f;
        if (e >= 0 && e < 128)
            v = fmaxf(fmaf(in[(pbase + lp) * 1024 + c * 128 + e], ssc[c], ssh[c]), 0.f);
        sx[lp][c][xi] = v;
    }
    __syncthreads();

    int lp = tid >> 7, e = tid & 127;
    float acc[8];
#pragma unroll
    for (int co = 0; co < 8; co++) acc[co] = b[co];

#pragma unroll
    for (int ci = 0; ci < 8; ci++) {
        float xw[15];
#pragma unroll
        for (int k = 0; k < 15; k++) xw[k] = sx[lp][ci][e + k];
#pragma unroll
        for (int k = 0; k < 15; k++)
#pragma unroll
            for (int co = 0; co < 8; co++)
                acc[co] = fmaf(sw[(co * 8 + ci) * 15 + k], xw[k], acc[co]);
    }

    int p = pbase + lp;
#pragma unroll
    for (int co = 0; co < 8; co++) out[p * 1024 + co * 128 + e] = acc[co];

    int lane = tid & 31;
#pragma unroll
    for (int co = 0; co < 8; co++) {
        float s = acc[co], ss = acc[co] * acc[co];
        for (int off = 16; off; off >>= 1) {
            s  += __shfl_down_sync(0xffffffffu, s,  off);
            ss += __shfl_down_sync(0xffffffffu, ss, off);
        }
        if (lane == 0) { atomicAdd(&sred[co], s); atomicAdd(&sred[8 + co], ss); }
    }
    __syncthreads();
    if (tid < 8) {
        atomicAdd(&g_stats[layer][tid],     (double)sred[tid]);
        atomicAdd(&g_stats[layer][8 + tid], (double)sred[8 + tid]);
    }
}

// ---- conv4: BN3+relu fused; 8->1, K=3, pad=1 ----
__global__ void __launch_bounds__(512) k_conv4(const float* __restrict__ w,
                                               const float* __restrict__ b,
                                               const float* __restrict__ gam,
                                               const float* __restrict__ bet) {
    __shared__ float sw[24];
    __shared__ float ssc[8], ssh[8];
    __shared__ float sx[4][8][130];
    __shared__ float sred[32];
    int tid = threadIdx.x;
    int pbase = blockIdx.x * 4;

    if (tid < 24) sw[tid] = w[tid];
    if (tid < 8) {
        double mu  = g_stats[2][tid] / CNT;
        double var = g_stats[2][8 + tid] / CNT - mu * mu;
        float sc = (float)((double)gam[tid] / sqrt(var + 1e-5));
        ssc[tid] = sc;
        ssh[tid] = bet[tid] - (float)mu * sc;
    }
    __syncthreads();

    for (int i = tid; i < 4 * 8 * 130; i += 512) {
        int lp = i / 1040, r = i % 1040, c = r / 130, xi = r % 130;
        int e = xi - 1;
        float v = 0.f;
        if (e >= 0 && e < 128)
            v = fmaxf(fmaf(g_actA[(pbase + lp) * 1024 + c * 128 + e], ssc[c], ssh[c]), 0.f);
        sx[lp][c][xi] = v;
    }
    __syncthreads();

    int lp = tid >> 7, e = tid & 127;
    float acc = b[0];
#pragma unroll
    for (int ci = 0; ci < 8; ci++)
#pragma unroll
        for (int k = 0; k < 3; k++)
            acc = fmaf(sw[ci * 3 + k], sx[lp][ci][e + k], acc);

    g_wraw[(pbase + lp) * 128 + e] = acc;

    float s = acc, ss = acc * acc;
    for (int off = 16; off; off >>= 1) {
        s  += __shfl_down_sync(0xffffffffu, s,  off);
        ss += __shfl_down_sync(0xffffffffu, ss, off);
    }
    int lane = tid & 31, wix = tid >> 5;
    if (lane == 0) { sred[wix] = s; sred[16 + wix] = ss; }
    __syncthreads();
    if (tid == 0) {
        float S = 0.f, SS = 0.f;
        for (int i = 0; i < 16; i++) { S += sred[i]; SS += sred[16 + i]; }
        atomicAdd(&g_stats[3][0], (double)S);
        atomicAdd(&g_stats[3][1], (double)SS);
    }
}

__global__ void k_final(const float* __restrict__ gam, const float* __restrict__ bet) {
    int p = blockIdx.x;
    int e = threadIdx.x;
    double mu  = g_stats[3][0] / CNT;
    double var = g_stats[3][1] / CNT - mu * mu;
    float sc = (float)((double)gam[0] / sqrt(var + 1e-5));
    float sh = bet[0] - (float)mu * sc;
    float wv = fmaxf(fmaf(g_wraw[p * 128 + e], sc, sh), 0.f);
    for (int off = 16; off; off >>= 1) wv += __shfl_down_sync(0xffffffffu, wv, off);
    __shared__ float sm[4];
    int lane = e & 31, w = e >> 5;
    if (lane == 0) sm[w] = wv;
    __syncthreads();
    if (e == 0) {
        float sW = sm[0] + sm[1] + sm[2] + sm[3];
        float cI = sW * g_sumI[p] * (1.0f / 128.0f);
        float cQ = sW * g_sumQ[p] * (1.0f / 128.0f);
        float mag = sqrtf(cI * cI + cQ * cQ);
        g_ydb[p] = 20.0f * log10f(mag + 1e-20f);
    }
}

__global__ void k_max() {
    float m = -CUDART_INF_F;
    for (int i = blockIdx.x * blockDim.x + threadIdx.x; i < NPIX; i += gridDim.x * blockDim.x)
        m = fmaxf(m, g_ydb[i]);
    for (int off = 16; off; off >>= 1) m = fmaxf(m, __shfl_down_sync(0xffffffffu, m, off));
    __shared__ float sm[8];
    int lane = threadIdx.x & 31, w = threadIdx.x >> 5;
    if (lane == 0) sm[w] = m;
    __syncthreads();
    if (threadIdx.x == 0) {
        float mm = sm[0];
        for (int i = 1; i < (int)(blockDim.x >> 5); i++) mm = fmaxf(mm, sm[i]);
        atomicMax(&g_maxydb, ford(mm));
    }
}

__global__ void k_sub(float* __restrict__ out) {
    int i = blockIdx.x * blockDim.x + threadIdx.x;
    unsigned u = g_maxydb;
    float mx = (u & 0x80000000u) ? __uint_as_float(u & 0x7fffffffu) : __uint_as_float(~u);
    if (i < NPIX) out[i] = g_ydb[i] - mx;
}

extern "C" void kernel_launch(void* const* d_in, const int* in_sizes, int n_in,
                              void* d_out, int out_size) {
    const float* idata     = (const float*)d_in[0];
    const float* qdata     = (const float*)d_in[1];
    const float* angles    = (const float*)d_in[2];
    const float* ele_pos   = (const float*)d_in[3];
    const float* time_zero = (const float*)d_in[4];
    const float* grid      = (const float*)d_in[5];
    const float* w1 = (const float*)d_in[6],  *b1 = (const float*)d_in[7];
    const float* g1 = (const float*)d_in[8],  *be1 = (const float*)d_in[9];
    const float* w2 = (const float*)d_in[10], *b2 = (const float*)d_in[11];
    const float* g2 = (const float*)d_in[12], *be2 = (const float*)d_in[13];
    const float* w3 = (const float*)d_in[14], *b3 = (const float*)d_in[15];
    const float* g3 = (const float*)d_in[16], *be3 = (const float*)d_in[17];
    const float* w4 = (const float*)d_in[18], *b4 = (const float*)d_in[19];
    const float* g4 = (const float*)d_in[20], *be4 = (const float*)d_in[21];
    float* out = (float*)d_out;

    k_init<<<1, 128>>>();
    k_nrm<<<1024, 256>>>(idata, qdata);
    k_bf<<<NPIX, 128>>>(idata, qdata, angles, ele_pos, time_zero, grid);
    k_conv1<<<NPIX / 4, 512>>>(w1, b1);
    k_conv23<<<NPIX / 4, 512>>>(w2, b2, g1, be1, 1, 0);  // BN1 on conv1 out; in A -> out B
    k_conv23<<<NPIX / 4, 512>>>(w3, b3, g2, be2, 2, 1);  // BN2 on conv2 out; in B -> out A
    k_conv4 <<<NPIX / 4, 512>>>(w4, b4, g3, be3);        // BN3 on conv3 out; in A -> wraw
    k_final<<<NPIX, 128>>>(g4, be4);
    k_max<<<64, 256>>>();
    k_sub<<<NPIX / 256, 256>>>(out);
}

// round 3
// speedup vs baseline: 1.3762x; 1.3762x over previous
#include <cuda_runtime.h>
#include <math.h>
#include <math_constants.h>

#define NPIX  32768      // 128*256 pixels
#define NE    128
#define NS    2048
#define NTOT  (16*128*2048)
#define CNT   4194304.0  // per-channel BN count = NPIX*NE

#define SK(x) ((x) + ((x) >> 3))   // shared skew: stride-8 lane access -> stride 9 (coprime to 32 banks)

// ---------------- scratch ----------------
__device__ float    g_act0[NPIX * 2 * NE];
__device__ float    g_actA[NPIX * 8 * NE];
__device__ float    g_actB[NPIX * 8 * NE];
__device__ float    g_wraw[NPIX * NE];
__device__ float    g_sumI[NPIX];
__device__ float    g_sumQ[NPIX];
__device__ float    g_ydb [NPIX];
__device__ unsigned g_maxsq;
__device__ unsigned g_maxydb;
__device__ double   g_stats[4][16];   // per-layer [sum(8) | sumsq(8)]

__device__ __forceinline__ unsigned ford(float f) {
    unsigned u = __float_as_uint(f);
    return (u & 0x80000000u) ? ~u : (u | 0x80000000u);
}

__global__ void k_init() {
    int t = threadIdx.x;
    if (t < 64) ((double*)g_stats)[t] = 0.0;
    if (t == 64) g_maxsq = 0u;
    if (t == 65) g_maxydb = 0u;
}

__global__ void k_nrm(const float* __restrict__ id, const float* __restrict__ qd) {
    float m = 0.f;
    for (int i = blockIdx.x * blockDim.x + threadIdx.x; i < NTOT; i += gridDim.x * blockDim.x) {
        float a = id[i], b = qd[i];
        m = fmaxf(m, a * a + b * b);
    }
    for (int off = 16; off; off >>= 1) m = fmaxf(m, __shfl_down_sync(0xffffffffu, m, off));
    __shared__ float sm[8];
    int lane = threadIdx.x & 31, w = threadIdx.x >> 5;
    if (lane == 0) sm[w] = m;
    __syncthreads();
    if (threadIdx.x == 0) {
        float mm = sm[0];
        for (int i = 1; i < (int)(blockDim.x >> 5); i++) mm = fmaxf(mm, sm[i]);
        atomicMax(&g_maxsq, __float_as_uint(mm));
    }
}

__global__ void k_bf(const float* __restrict__ idata, const float* __restrict__ qdata,
                     const float* __restrict__ angles, const float* __restrict__ ele_pos,
                     const float* __restrict__ time_zero, const float* __restrict__ grid) {
    int p = blockIdx.x;
    int e = threadIdx.x;
    float x = grid[p * 3 + 0];
    float z = grid[p * 3 + 2];
    float ang = angles[0];
    float sA, cA;
    sincosf(ang, &sA, &cA);
    float ex  = ele_pos[e * 3];
    float ex0 = ele_pos[0];
    float exL = ele_pos[(NE - 1) * 3];

    const float FSC = (float)(20832000.0 / 1540.0);
    float txdel = (x * sA + z * cA + time_zero[0] * 1540.0f) * FSC;
    float vx = x - ex;
    float dist = sqrtf(vx * vx + z * z);
    float delays = txdel + dist * FSC;
    float d0 = floorf(delays);
    float frac = delays - d0;
    int i0 = (int)d0;

    const float* is = idata + e * NS;
    const float* qs = qdata + e * NS;
    float iv0 = (i0 >= 0 && i0 < NS)         ? is[i0]     : 0.f;
    float iv1 = (i0 + 1 >= 0 && i0 + 1 < NS) ? is[i0 + 1] : 0.f;
    float qv0 = (i0 >= 0 && i0 < NS)         ? qs[i0]     : 0.f;
    float qv1 = (i0 + 1 >= 0 && i0 + 1 < NS) ? qs[i0 + 1] : 0.f;

    float invn = rsqrtf(__uint_as_float(g_maxsq));
    float ifoc = (iv0 * (1.f - frac) + iv1 * frac) * invn;
    float qfoc = (qv0 * (1.f - frac) + qv1 * frac) * invn;

    float tshift = delays / 20832000.0f - (z * 2.0f) / 1540.0f;
    float theta = (float)(2.0 * CUDART_PI * 5208000.0) * tshift;
    float st, ct;
    sincosf(theta, &st, &ct);
    float ir = ifoc * ct - qfoc * st;
    float qr = qfoc * ct + ifoc * st;

    float avx = fabsf(vx);
    bool mrx = (fabsf(z) > avx) || (avx <= 0.001f) ||
               ((vx >= 0.001f)  && (x <= ex0)) ||
               ((vx <= -0.001f) && (x >= exL));
    float xp = x - z * tanf(ang);
    bool mtx = (xp >= ex0 * 1.2f) && (xp <= exL * 1.2f);
    if (!(mrx && mtx)) { ir = 0.f; qr = 0.f; }

    g_act0[p * 256 + e]       = ir;
    g_act0[p * 256 + 128 + e] = qr;

    float si = ir, sq = qr;
    for (int off = 16; off; off >>= 1) {
        si += __shfl_down_sync(0xffffffffu, si, off);
        sq += __shfl_down_sync(0xffffffffu, sq, off);
    }
    __shared__ float sI[4], sQ[4];
    int lane = e & 31, w = e >> 5;
    if (lane == 0) { sI[w] = si; sQ[w] = sq; }
    __syncthreads();
    if (e == 0) {
        g_sumI[p] = sI[0] + sI[1] + sI[2] + sI[3];
        g_sumQ[p] = sQ[0] + sQ[1] + sQ[2] + sQ[3];
    }
}

// ---- conv1: 2->8, K=65, pad=32. Thread = (pixel, co, 8 e's); register-blocked. ----
__global__ void __launch_bounds__(256, 4) k_conv1(const float* __restrict__ w,
                                                  const float* __restrict__ b) {
    __shared__ float sw[1040];
    __shared__ float sx[2][2][216];   // SK(191)=214
    __shared__ float sred[16];
    int tid = threadIdx.x;
    int pbase = blockIdx.x * 2;

    for (int i = tid; i < 1040; i += 256) sw[i] = w[i];
    if (tid < 16) sred[tid] = 0.f;
    for (int i = tid; i < 2 * 2 * 192; i += 256) {
        int lp = i / 384, r = i % 384, c = r / 192, xi = r % 192;
        int e = xi - 32;
        sx[lp][c][SK(xi)] = (e >= 0 && e < 128) ? g_act0[(pbase + lp) * 256 + c * 128 + e] : 0.f;
    }
    __syncthreads();

    int lp = tid >> 7, t = tid & 127, co = t >> 4, e0 = (t & 15) * 8;
    float acc[8];
    float bias = b[co];
#pragma unroll
    for (int j = 0; j < 8; j++) acc[j] = bias;

#pragma unroll
    for (int ci = 0; ci < 2; ci++) {
        const float* wc = &sw[(co * 2 + ci) * 65];
        const float* sp = &sx[lp][ci][0];
#pragma unroll
        for (int kb = 0; kb < 64; kb += 8) {
            float wr[8], ar[15];
#pragma unroll
            for (int k = 0; k < 8; k++)  wr[k] = wc[kb + k];
#pragma unroll
            for (int k = 0; k < 15; k++) ar[k] = sp[SK(e0 + kb + k)];
#pragma unroll
            for (int k = 0; k < 8; k++)
#pragma unroll
                for (int j = 0; j < 8; j++) acc[j] = fmaf(wr[k], ar[k + j], acc[j]);
        }
        float wl = wc[64];
#pragma unroll
        for (int j = 0; j < 8; j++) acc[j] = fmaf(wl, sp[SK(e0 + 64 + j)], acc[j]);
    }

    int p = pbase + lp;
    float s = 0.f, ss = 0.f;
#pragma unroll
    for (int j = 0; j < 8; j++) {
        g_actA[p * 1024 + co * 128 + e0 + j] = acc[j];
        s += acc[j];
        ss += acc[j] * acc[j];
    }
    for (int off = 8; off; off >>= 1) {
        s  += __shfl_down_sync(0xffffffffu, s,  off, 16);
        ss += __shfl_down_sync(0xffffffffu, ss, off, 16);
    }
    if ((t & 15) == 0) { atomicAdd(&sred[co], s); atomicAdd(&sred[8 + co], ss); }
    __syncthreads();
    if (tid < 8) {
        atomicAdd(&g_stats[0][tid],     (double)sred[tid]);
        atomicAdd(&g_stats[0][8 + tid], (double)sred[8 + tid]);
    }
}

// ---- conv2/3: BN(prev)+relu fused on load; 8->8, K=15, pad=7; register-blocked ----
__global__ void __launch_bounds__(256, 4) k_conv23(const float* __restrict__ w,
                                                   const float* __restrict__ b,
                                                   const float* __restrict__ gam,
                                                   const float* __restrict__ bet,
                                                   int layer, int flip) {
    __shared__ float sw[960];
    __shared__ float ssc[8], ssh[8];
    __shared__ float sx[2][8][160];   // SK(141)=158
    __shared__ float sred[16];
    const float* in  = flip ? g_actB : g_actA;
    float*       out = flip ? g_actA : g_actB;

    int tid = threadIdx.x;
    int pbase = blockIdx.x * 2;

    for (int i = tid; i < 960; i += 256) sw[i] = w[i];
    if (tid < 8) {
        double mu  = g_stats[layer - 1][tid] / CNT;
        double var = g_stats[layer - 1][8 + tid] / CNT - mu * mu;
        float sc = (float)((double)gam[tid] / sqrt(var + 1e-5));
        ssc[tid] = sc;
        ssh[tid] = bet[tid] - (float)mu * sc;
    }
    if (tid < 16) sred[tid] = 0.f;
    __syncthreads();

    for (int i = tid; i < 2 * 8 * 142; i += 256) {
        int lp = i / 1136, r = i % 1136, c = r / 142, xi = r % 142;
        int e = xi - 7;
        float v = 0.f;
        if (e >= 0 && e < 128)
            v = fmaxf(fmaf(in[(pbase + lp) * 1024 + c * 128 + e], ssc[c], ssh[c]), 0.f);
        sx[lp][c][SK(xi)] = v;
    }
    __syncthreads();

    int lp = tid >> 7, t = tid & 127, co = t >> 4, e0 = (t & 15) * 8;
    float acc[8];
    float bias = b[co];
#pragma unroll
    for (int j = 0; j < 8; j++) acc[j] = bias;

#pragma unroll
    for (int ci = 0; ci < 8; ci++) {
        const float* wc = &sw[(co * 8 + ci) * 15];
        const float* sp = &sx[lp][ci][0];
        float wr[15], ar[22];
#pragma unroll
        for (int k = 0; k < 15; k++) wr[k] = wc[k];
#pragma unroll
        for (int k = 0; k < 22; k++) ar[k] = sp[SK(e0 + k)];
#pragma unroll
        for (int k = 0; k < 15; k++)
#pragma unroll
            for (int j = 0; j < 8; j++) acc[j] = fmaf(wr[k], ar[k + j], acc[j]);
    }

    int p = pbase + lp;
    float s = 0.f, ss = 0.f;
#pragma unroll
    for (int j = 0; j < 8; j++) {
        out[p * 1024 + co * 128 + e0 + j] = acc[j];
        s += acc[j];
        ss += acc[j] * acc[j];
    }
    for (int off = 8; off; off >>= 1) {
        s  += __shfl_down_sync(0xffffffffu, s,  off, 16);
        ss += __shfl_down_sync(0xffffffffu, ss, off, 16);
    }
    if ((t & 15) == 0) { atomicAdd(&sred[co], s); atomicAdd(&sred[8 + co], ss); }
    __syncthreads();
    if (tid < 8) {
        atomicAdd(&g_stats[layer][tid],     (double)sred[tid]);
        atomicAdd(&g_stats[layer][8 + tid], (double)sred[8 + tid]);
    }
}

// ---- conv4: BN3+relu fused; 8->1, K=3, pad=1 (unchanged from passing R2) ----
__global__ void __launch_bounds__(512) k_conv4(const float* __restrict__ w,
                                               const float* __restrict__ b,
                                               const float* __restrict__ gam,
                                               const float* __restrict__ bet) {
    __shared__ float sw[24];
    __shared__ float ssc[8], ssh[8];
    __shared__ float sx[4][8][130];
    __shared__ float sred[32];
    int tid = threadIdx.x;
    int pbase = blockIdx.x * 4;

    if (tid < 24) sw[tid] = w[tid];
    if (tid < 8) {
        double mu  = g_stats[2][tid] / CNT;
        double var = g_stats[2][8 + tid] / CNT - mu * mu;
        float sc = (float)((double)gam[tid] / sqrt(var + 1e-5));
        ssc[tid] = sc;
        ssh[tid] = bet[tid] - (float)mu * sc;
    }
    __syncthreads();

    for (int i = tid; i < 4 * 8 * 130; i += 512) {
        int lp = i / 1040, r = i % 1040, c = r / 130, xi = r % 130;
        int e = xi - 1;
        float v = 0.f;
        if (e >= 0 && e < 128)
            v = fmaxf(fmaf(g_actA[(pbase + lp) * 1024 + c * 128 + e], ssc[c], ssh[c]), 0.f);
        sx[lp][c][xi] = v;
    }
    __syncthreads();

    int lp = tid >> 7, e = tid & 127;
    float acc = b[0];
#pragma unroll
    for (int ci = 0; ci < 8; ci++)
#pragma unroll
        for (int k = 0; k < 3; k++)
            acc = fmaf(sw[ci * 3 + k], sx[lp][ci][e + k], acc);

    g_wraw[(pbase + lp) * 128 + e] = acc;

    float s = acc, ss = acc * acc;
    for (int off = 16; off; off >>= 1) {
        s  += __shfl_down_sync(0xffffffffu, s,  off);
        ss += __shfl_down_sync(0xffffffffu, ss, off);
    }
    int lane = tid & 31, wix = tid >> 5;
    if (lane == 0) { sred[wix] = s; sred[16 + wix] = ss; }
    __syncthreads();
    if (tid == 0) {
        float S = 0.f, SS = 0.f;
        for (int i = 0; i < 16; i++) { S += sred[i]; SS += sred[16 + i]; }
        atomicAdd(&g_stats[3][0], (double)S);
        atomicAdd(&g_stats[3][1], (double)SS);
    }
}

__global__ void k_final(const float* __restrict__ gam, const float* __restrict__ bet) {
    int p = blockIdx.x;
    int e = threadIdx.x;
    double mu  = g_stats[3][0] / CNT;
    double var = g_stats[3][1] / CNT - mu * mu;
    float sc = (float)((double)gam[0] / sqrt(var + 1e-5));
    float sh = bet[0] - (float)mu * sc;
    float wv = fmaxf(fmaf(g_wraw[p * 128 + e], sc, sh), 0.f);
    for (int off = 16; off; off >>= 1) wv += __shfl_down_sync(0xffffffffu, wv, off);
    __shared__ float sm[4];
    int lane = e & 31, w = e >> 5;
    if (lane == 0) sm[w] = wv;
    __syncthreads();
    if (e == 0) {
        float sW = sm[0] + sm[1] + sm[2] + sm[3];
        float cI = sW * g_sumI[p] * (1.0f / 128.0f);
        float cQ = sW * g_sumQ[p] * (1.0f / 128.0f);
        float mag = sqrtf(cI * cI + cQ * cQ);
        g_ydb[p] = 20.0f * log10f(mag + 1e-20f);
    }
}

__global__ void k_max() {
    float m = -CUDART_INF_F;
    for (int i = blockIdx.x * blockDim.x + threadIdx.x; i < NPIX; i += gridDim.x * blockDim.x)
        m = fmaxf(m, g_ydb[i]);
    for (int off = 16; off; off >>= 1) m = fmaxf(m, __shfl_down_sync(0xffffffffu, m, off));
    __shared__ float sm[8];
    int lane = threadIdx.x & 31, w = threadIdx.x >> 5;
    if (lane == 0) sm[w] = m;
    __syncthreads();
    if (threadIdx.x == 0) {
        float mm = sm[0];
        for (int i = 1; i < (int)(blockDim.x >> 5); i++) mm = fmaxf(mm, sm[i]);
        atomicMax(&g_maxydb, ford(mm));
    }
}

__global__ void k_sub(float* __restrict__ out) {
    int i = blockIdx.x * blockDim.x + threadIdx.x;
    unsigned u = g_maxydb;
    float mx = (u & 0x80000000u) ? __uint_as_float(u & 0x7fffffffu) : __uint_as_float(~u);
    if (i < NPIX) out[i] = g_ydb[i] - mx;
}

extern "C" void kernel_launch(void* const* d_in, const int* in_sizes, int n_in,
                              void* d_out, int out_size) {
    const float* idata     = (const float*)d_in[0];
    const float* qdata     = (const float*)d_in[1];
    const float* angles    = (const float*)d_in[2];
    const float* ele_pos   = (const float*)d_in[3];
    const float* time_zero = (const float*)d_in[4];
    const float* grid      = (const float*)d_in[5];
    const float* w1 = (const float*)d_in[6],  *b1 = (const float*)d_in[7];
    const float* g1 = (const float*)d_in[8],  *be1 = (const float*)d_in[9];
    const float* w2 = (const float*)d_in[10], *b2 = (const float*)d_in[11];
    const float* g2 = (const float*)d_in[12], *be2 = (const float*)d_in[13];
    const float* w3 = (const float*)d_in[14], *b3 = (const float*)d_in[15];
    const float* g3 = (const float*)d_in[16], *be3 = (const float*)d_in[17];
    const float* w4 = (const float*)d_in[18], *b4 = (const float*)d_in[19];
    const float* g4 = (const float*)d_in[20], *be4 = (const float*)d_in[21];
    float* out = (float*)d_out;

    k_init<<<1, 128>>>();
    k_nrm<<<1024, 256>>>(idata, qdata);
    k_bf<<<NPIX, 128>>>(idata, qdata, angles, ele_pos, time_zero, grid);
    k_conv1<<<NPIX / 2, 256>>>(w1, b1);
    k_conv23<<<NPIX / 2, 256>>>(w2, b2, g1, be1, 1, 0);  // BN1; in A -> out B
    k_conv23<<<NPIX / 2, 256>>>(w3, b3, g2, be2, 2, 1);  // BN2; in B -> out A
    k_conv4 <<<NPIX / 4, 512>>>(w4, b4, g3, be3);        // BN3; in A -> wraw
    k_final<<<NPIX, 128>>>(g4, be4);
    k_max<<<64, 256>>>();
    k_sub<<<NPIX / 256, 256>>>(out);
}

// round 4
// speedup vs baseline: 1.5309x; 1.1124x over previous
#include <cuda_runtime.h>
#include <math.h>
#include <math_constants.h>

#define NPIX  32768      // 128*256 pixels
#define NE    128
#define NS    2048
#define NTOT  (16*128*2048)
#define CNT   4194304.0  // per-channel BN count = NPIX*NE

typedef unsigned long long u64;

// ---------------- scratch ----------------
__device__ float    g_act0[NPIX * 2 * NE];
__device__ float    g_actA[NPIX * 8 * NE];
__device__ float    g_actB[NPIX * 8 * NE];
__device__ float    g_wraw[NPIX * NE];
__device__ float    g_sumI[NPIX];
__device__ float    g_sumQ[NPIX];
__device__ float    g_ydb [NPIX];
__device__ unsigned g_maxsq;
__device__ unsigned g_maxydb;
__device__ double   g_stats[4][16];   // per-layer [sum(8) | sumsq(8)]

__device__ __forceinline__ unsigned ford(float f) {
    unsigned u = __float_as_uint(f);
    return (u & 0x80000000u) ? ~u : (u | 0x80000000u);
}

// packed fp32x2 helpers
__device__ __forceinline__ u64 ffma2(u64 a, u64 b, u64 c) {
    u64 d;
    asm("fma.rn.f32x2 %0,%1,%2,%3;" : "=l"(d) : "l"(a), "l"(b), "l"(c));
    return d;
}
__device__ __forceinline__ u64 pack2(float lo, float hi) {
    u64 d;
    asm("mov.b64 %0,{%1,%2};" : "=l"(d) : "f"(lo), "f"(hi));
    return d;
}
__device__ __forceinline__ void unpack2(u64 a, float& lo, float& hi) {
    asm("mov.b64 {%0,%1},%2;" : "=f"(lo), "=f"(hi) : "l"(a));
}
// returns (lo = a.hi, hi = b.lo)
__device__ __forceinline__ u64 pack_hl(u64 a, u64 b) {
    u64 d;
    asm("{ .reg .b32 al,ah,bl,bh;\n\t"
        "mov.b64 {al,ah},%1;\n\t"
        "mov.b64 {bl,bh},%2;\n\t"
        "mov.b64 %0,{ah,bl}; }" : "=l"(d) : "l"(a), "l"(b));
    return d;
}

__global__ void k_init() {
    int t = threadIdx.x;
    if (t < 64) ((double*)g_stats)[t] = 0.0;
    if (t == 64) g_maxsq = 0u;
    if (t == 65) g_maxydb = 0u;
}

__global__ void k_nrm(const float* __restrict__ id, const float* __restrict__ qd) {
    float m = 0.f;
    for (int i = blockIdx.x * blockDim.x + threadIdx.x; i < NTOT; i += gridDim.x * blockDim.x) {
        float a = id[i], b = qd[i];
        m = fmaxf(m, a * a + b * b);
    }
    for (int off = 16; off; off >>= 1) m = fmaxf(m, __shfl_down_sync(0xffffffffu, m, off));
    __shared__ float sm[8];
    int lane = threadIdx.x & 31, w = threadIdx.x >> 5;
    if (lane == 0) sm[w] = m;
    __syncthreads();
    if (threadIdx.x == 0) {
        float mm = sm[0];
        for (int i = 1; i < (int)(blockDim.x >> 5); i++) mm = fmaxf(mm, sm[i]);
        atomicMax(&g_maxsq, __float_as_uint(mm));
    }
}

__global__ void k_bf(const float* __restrict__ idata, const float* __restrict__ qdata,
                     const float* __restrict__ angles, const float* __restrict__ ele_pos,
                     const float* __restrict__ time_zero, const float* __restrict__ grid) {
    int p = blockIdx.x;
    int e = threadIdx.x;
    float x = grid[p * 3 + 0];
    float z = grid[p * 3 + 2];
    float ang = angles[0];
    float sA, cA;
    sincosf(ang, &sA, &cA);
    float ex  = ele_pos[e * 3];
    float ex0 = ele_pos[0];
    float exL = ele_pos[(NE - 1) * 3];

    const float FSC = (float)(20832000.0 / 1540.0);
    float txdel = (x * sA + z * cA + time_zero[0] * 1540.0f) * FSC;
    float vx = x - ex;
    float dist = sqrtf(vx * vx + z * z);
    float delays = txdel + dist * FSC;
    float d0 = floorf(delays);
    float frac = delays - d0;
    int i0 = (int)d0;

    const float* is = idata + e * NS;
    const float* qs = qdata + e * NS;
    float iv0 = (i0 >= 0 && i0 < NS)         ? is[i0]     : 0.f;
    float iv1 = (i0 + 1 >= 0 && i0 + 1 < NS) ? is[i0 + 1] : 0.f;
    float qv0 = (i0 >= 0 && i0 < NS)         ? qs[i0]     : 0.f;
    float qv1 = (i0 + 1 >= 0 && i0 + 1 < NS) ? qs[i0 + 1] : 0.f;

    float invn = rsqrtf(__uint_as_float(g_maxsq));
    float ifoc = (iv0 * (1.f - frac) + iv1 * frac) * invn;
    float qfoc = (qv0 * (1.f - frac) + qv1 * frac) * invn;

    float tshift = delays / 20832000.0f - (z * 2.0f) / 1540.0f;
    float theta = (float)(2.0 * CUDART_PI * 5208000.0) * tshift;
    float st, ct;
    sincosf(theta, &st, &ct);
    float ir = ifoc * ct - qfoc * st;
    float qr = qfoc * ct + ifoc * st;

    float avx = fabsf(vx);
    bool mrx = (fabsf(z) > avx) || (avx <= 0.001f) ||
               ((vx >= 0.001f)  && (x <= ex0)) ||
               ((vx <= -0.001f) && (x >= exL));
    float xp = x - z * tanf(ang);
    bool mtx = (xp >= ex0 * 1.2f) && (xp <= exL * 1.2f);
    if (!(mrx && mtx)) { ir = 0.f; qr = 0.f; }

    g_act0[p * 256 + e]       = ir;
    g_act0[p * 256 + 128 + e] = qr;

    float si = ir, sq = qr;
    for (int off = 16; off; off >>= 1) {
        si += __shfl_down_sync(0xffffffffu, si, off);
        sq += __shfl_down_sync(0xffffffffu, sq, off);
    }
    __shared__ float sI[4], sQ[4];
    int lane = e & 31, w = e >> 5;
    if (lane == 0) { sI[w] = si; sQ[w] = sq; }
    __syncthreads();
    if (e == 0) {
        g_sumI[p] = sI[0] + sI[1] + sI[2] + sI[3];
        g_sumQ[p] = sQ[0] + sQ[1] + sQ[2] + sQ[3];
    }
}

// ============ conv1: 2->8, K=65, pad=32; f32x2 packed, immediate-offset LDS ============
// thread = (pixel lp, co, 8-wide e-group); window logical x in [0,192), e = x-32.
__global__ void __launch_bounds__(256, 4) k_conv1(const float* __restrict__ w,
                                                  const float* __restrict__ b) {
    __shared__ float2 swd[1040];       // weights duplicated (w,w), [co][ci][k]
    __shared__ float2 sx2[2][2][122];  // pair-skewed activations; PS(95)=118
    __shared__ float  sred[16];
    int tid = threadIdx.x;
    int pbase = blockIdx.x * 2;

    for (int i = tid; i < 1040; i += 256) { float v = w[i]; swd[i] = make_float2(v, v); }
    if (tid < 16) sred[tid] = 0.f;
    for (int i = tid; i < 2 * 2 * 192; i += 256) {
        int lp = i / 384, r = i % 384, c = r / 192, x = r % 192;
        int e = x - 32;
        float v = (e >= 0 && e < 128) ? g_act0[(pbase + lp) * 256 + c * 128 + e] : 0.f;
        int P = x >> 1;
        ((float*)&sx2[lp][c][P + (P >> 2)])[x & 1] = v;
    }
    __syncthreads();

    int lp = tid >> 7, t = tid & 127, co = t >> 4, g = (t & 15); // e0 = 8g
    int psb = 5 * g;                                             // PS(4g)
    float bias = b[co];
    u64 acc[4];
#pragma unroll
    for (int m = 0; m < 4; m++) acc[m] = pack2(bias, bias);

#pragma unroll
    for (int ci = 0; ci < 2; ci++) {
        const u64* wp = (const u64*)&swd[(co * 2 + ci) * 65];
        const u64* spc = (const u64*)&sx2[lp][ci][psb];
#pragma unroll
        for (int kb = 0; kb < 64; kb += 8) {
            const u64* sp = spc + (kb / 2 + kb / 8);  // PS advance for pair offset kb/2 (mult of 4)
            u64 pe[8], po[7];
#pragma unroll
            for (int i = 0; i < 8; i++) pe[i] = sp[i + (i >> 2)];
#pragma unroll
            for (int i = 0; i < 7; i++) po[i] = pack_hl(pe[i], pe[i + 1]);
#pragma unroll
            for (int q = 0; q < 4; q++) {
                u64 we = wp[kb + 2 * q];
#pragma unroll
                for (int m = 0; m < 4; m++) acc[m] = ffma2(we, pe[q + m], acc[m]);
                u64 wo = wp[kb + 2 * q + 1];
#pragma unroll
                for (int m = 0; m < 4; m++) acc[m] = ffma2(wo, po[q + m], acc[m]);
            }
        }
        { // last tap k=64 (even)
            const u64* sp = spc + 40;  // kb/2 + kb/8 for kb=64
            u64 wl = wp[64];
#pragma unroll
            for (int m = 0; m < 4; m++) acc[m] = ffma2(wl, sp[m], acc[m]);
        }
    }

    int p = pbase + lp;
    u64* outp = (u64*)&g_actA[p * 1024 + co * 128 + g * 8];
    float s = 0.f, ss = 0.f;
#pragma unroll
    for (int m = 0; m < 4; m++) {
        outp[m] = acc[m];
        float f0, f1; unpack2(acc[m], f0, f1);
        s += f0 + f1; ss += f0 * f0 + f1 * f1;
    }
    for (int off = 8; off; off >>= 1) {
        s  += __shfl_down_sync(0xffffffffu, s,  off, 16);
        ss += __shfl_down_sync(0xffffffffu, ss, off, 16);
    }
    if ((t & 15) == 0) { atomicAdd(&sred[co], s); atomicAdd(&sred[8 + co], ss); }
    __syncthreads();
    if (tid < 8) {
        atomicAdd(&g_stats[0][tid],     (double)sred[tid]);
        atomicAdd(&g_stats[0][8 + tid], (double)sred[8 + tid]);
    }
}

// ============ conv2/3: BN(prev)+relu on load; 8->8, K=15, pad=7; f32x2 packed ============
__global__ void __launch_bounds__(256, 4) k_conv23(const float* __restrict__ w,
                                                   const float* __restrict__ b,
                                                   const float* __restrict__ gam,
                                                   const float* __restrict__ bet,
                                                   int layer, int flip) {
    __shared__ float2 swd[960];        // duplicated weights [co][ci][k]
    __shared__ float2 sx2[2][8][90];   // pair-skewed; PS(70)=87
    __shared__ float  ssc[8], ssh[8];
    __shared__ float  sred[16];
    const float* in  = flip ? g_actB : g_actA;
    float*       out = flip ? g_actA : g_actB;

    int tid = threadIdx.x;
    int pbase = blockIdx.x * 2;

    for (int i = tid; i < 960; i += 256) { float v = w[i]; swd[i] = make_float2(v, v); }
    if (tid < 8) {
        double mu  = g_stats[layer - 1][tid] / CNT;
        double var = g_stats[layer - 1][8 + tid] / CNT - mu * mu;
        float sc = (float)((double)gam[tid] / sqrt(var + 1e-5));
        ssc[tid] = sc;
        ssh[tid] = bet[tid] - (float)mu * sc;
    }
    if (tid < 16) sred[tid] = 0.f;
    __syncthreads();

    for (int i = tid; i < 2 * 8 * 142; i += 256) {
        int lp = i / 1136, r = i % 1136, c = r / 142, x = r % 142;
        int e = x - 7;
        float v = 0.f;
        if (e >= 0 && e < 128)
            v = fmaxf(fmaf(in[(pbase + lp) * 1024 + c * 128 + e], ssc[c], ssh[c]), 0.f);
        int P = x >> 1;
        ((float*)&sx2[lp][c][P + (P >> 2)])[x & 1] = v;
    }
    __syncthreads();

    int lp = tid >> 7, t = tid & 127, co = t >> 4, g = (t & 15);
    int psb = 5 * g;  // PS(4g)
    float bias = b[co];
    u64 acc[4];
#pragma unroll
    for (int m = 0; m < 4; m++) acc[m] = pack2(bias, bias);

#pragma unroll
    for (int ci = 0; ci < 8; ci++) {
        const u64* sp = (const u64*)&sx2[lp][ci][psb];
        const u64* wp = (const u64*)&swd[(co * 8 + ci) * 15];
        u64 pe[11], po[10];
#pragma unroll
        for (int i = 0; i < 11; i++) pe[i] = sp[i + (i >> 2)];
#pragma unroll
        for (int i = 0; i < 10; i++) po[i] = pack_hl(pe[i], pe[i + 1]);
#pragma unroll
        for (int q = 0; q < 8; q++) {
            u64 we = wp[2 * q];
#pragma unroll
            for (int m = 0; m < 4; m++) acc[m] = ffma2(we, pe[q + m], acc[m]);
            if (q < 7) {
                u64 wo = wp[2 * q + 1];
#pragma unroll
                for (int m = 0; m < 4; m++) acc[m] = ffma2(wo, po[q + m], acc[m]);
            }
        }
    }

    int p = pbase + lp;
    u64* outp = (u64*)&out[p * 1024 + co * 128 + g * 8];
    float s = 0.f, ss = 0.f;
#pragma unroll
    for (int m = 0; m < 4; m++) {
        outp[m] = acc[m];
        float f0, f1; unpack2(acc[m], f0, f1);
        s += f0 + f1; ss += f0 * f0 + f1 * f1;
    }
    for (int off = 8; off; off >>= 1) {
        s  += __shfl_down_sync(0xffffffffu, s,  off, 16);
        ss += __shfl_down_sync(0xffffffffu, ss, off, 16);
    }
    if ((t & 15) == 0) { atomicAdd(&sred[co], s); atomicAdd(&sred[8 + co], ss); }
    __syncthreads();
    if (tid < 8) {
        atomicAdd(&g_stats[layer][tid],     (double)sred[tid]);
        atomicAdd(&g_stats[layer][8 + tid], (double)sred[8 + tid]);
    }
}

// ---- conv4: BN3+relu fused; 8->1, K=3, pad=1 ----
__global__ void __launch_bounds__(512) k_conv4(const float* __restrict__ w,
                                               const float* __restrict__ b,
                                               const float* __restrict__ gam,
                                               const float* __restrict__ bet) {
    __shared__ float sw[24];
    __shared__ float ssc[8], ssh[8];
    __shared__ float sx[4][8][130];
    __shared__ float sred[32];
    int tid = threadIdx.x;
    int pbase = blockIdx.x * 4;

    if (tid < 24) sw[tid] = w[tid];
    if (tid < 8) {
        double mu  = g_stats[2][tid] / CNT;
        double var = g_stats[2][8 + tid] / CNT - mu * mu;
        float sc = (float)((double)gam[tid] / sqrt(var + 1e-5));
        ssc[tid] = sc;
        ssh[tid] = bet[tid] - (float)mu * sc;
    }
    __syncthreads();

    for (int i = tid; i < 4 * 8 * 130; i += 512) {
        int lp = i / 1040, r = i % 1040, c = r / 130, xi = r % 130;
        int e = xi - 1;
        float v = 0.f;
        if (e >= 0 && e < 128)
            v = fmaxf(fmaf(g_actA[(pbase + lp) * 1024 + c * 128 + e], ssc[c], ssh[c]), 0.f);
        sx[lp][c][xi] = v;
    }
    __syncthreads();

    int lp = tid >> 7, e = tid & 127;
    float acc = b[0];
#pragma unroll
    for (int ci = 0; ci < 8; ci++)
#pragma unroll
        for (int k = 0; k < 3; k++)
            acc = fmaf(sw[ci * 3 + k], sx[lp][ci][e + k], acc);

    g_wraw[(pbase + lp) * 128 + e] = acc;

    float s = acc, ss = acc * acc;
    for (int off = 16; off; off >>= 1) {
        s  += __shfl_down_sync(0xffffffffu, s,  off);
        ss += __shfl_down_sync(0xffffffffu, ss, off);
    }
    int lane = tid & 31, wix = tid >> 5;
    if (lane == 0) { sred[wix] = s; sred[16 + wix] = ss; }
    __syncthreads();
    if (tid == 0) {
        float S = 0.f, SS = 0.f;
        for (int i = 0; i < 16; i++) { S += sred[i]; SS += sred[16 + i]; }
        atomicAdd(&g_stats[3][0], (double)S);
        atomicAdd(&g_stats[3][1], (double)SS);
    }
}

__global__ void k_final(const float* __restrict__ gam, const float* __restrict__ bet) {
    int p = blockIdx.x;
    int e = threadIdx.x;
    double mu  = g_stats[3][0] / CNT;
    double var = g_stats[3][1] / CNT - mu * mu;
    float sc = (float)((double)gam[0] / sqrt(var + 1e-5));
    float sh = bet[0] - (float)mu * sc;
    float wv = fmaxf(fmaf(g_wraw[p * 128 + e], sc, sh), 0.f);
    for (int off = 16; off; off >>= 1) wv += __shfl_down_sync(0xffffffffu, wv, off);
    __shared__ float sm[4];
    int lane = e & 31, w = e >> 5;
    if (lane == 0) sm[w] = wv;
    __syncthreads();
    if (e == 0) {
        float sW = sm[0] + sm[1] + sm[2] + sm[3];
        float cI = sW * g_sumI[p] * (1.0f / 128.0f);
        float cQ = sW * g_sumQ[p] * (1.0f / 128.0f);
        float mag = sqrtf(cI * cI + cQ * cQ);
        g_ydb[p] = 20.0f * log10f(mag + 1e-20f);
    }
}

__global__ void k_max() {
    float m = -CUDART_INF_F;
    for (int i = blockIdx.x * blockDim.x + threadIdx.x; i < NPIX; i += gridDim.x * blockDim.x)
        m = fmaxf(m, g_ydb[i]);
    for (int off = 16; off; off >>= 1) m = fmaxf(m, __shfl_down_sync(0xffffffffu, m, off));
    __shared__ float sm[8];
    int lane = threadIdx.x & 31, w = threadIdx.x >> 5;
    if (lane == 0) sm[w] = m;
    __syncthreads();
    if (threadIdx.x == 0) {
        float mm = sm[0];
        for (int i = 1; i < (int)(blockDim.x >> 5); i++) mm = fmaxf(mm, sm[i]);
        atomicMax(&g_maxydb, ford(mm));
    }
}

__global__ void k_sub(float* __restrict__ out) {
    int i = blockIdx.x * blockDim.x + threadIdx.x;
    unsigned u = g_maxydb;
    float mx = (u & 0x80000000u) ? __uint_as_float(u & 0x7fffffffu) : __uint_as_float(~u);
    if (i < NPIX) out[i] = g_ydb[i] - mx;
}

extern "C" void kernel_launch(void* const* d_in, const int* in_sizes, int n_in,
                              void* d_out, int out_size) {
    const float* idata     = (const float*)d_in[0];
    const float* qdata     = (const float*)d_in[1];
    const float* angles    = (const float*)d_in[2];
    const float* ele_pos   = (const float*)d_in[3];
    const float* time_zero = (const float*)d_in[4];
    const float* grid      = (const float*)d_in[5];
    const float* w1 = (const float*)d_in[6],  *b1 = (const float*)d_in[7];
    const float* g1 = (const float*)d_in[8],  *be1 = (const float*)d_in[9];
    const float* w2 = (const float*)d_in[10], *b2 = (const float*)d_in[11];
    const float* g2 = (const float*)d_in[12], *be2 = (const float*)d_in[13];
    const float* w3 = (const float*)d_in[14], *b3 = (const float*)d_in[15];
    const float* g3 = (const float*)d_in[16], *be3 = (const float*)d_in[17];
    const float* w4 = (const float*)d_in[18], *b4 = (const float*)d_in[19];
    const float* g4 = (const float*)d_in[20], *be4 = (const float*)d_in[21];
    float* out = (float*)d_out;

    k_init<<<1, 128>>>();
    k_nrm<<<1024, 256>>>(idata, qdata);
    k_bf<<<NPIX, 128>>>(idata, qdata, angles, ele_pos, time_zero, grid);
    k_conv1<<<NPIX / 2, 256>>>(w1, b1);
    k_conv23<<<NPIX / 2, 256>>>(w2, b2, g1, be1, 1, 0);  // BN1; in A -> out B
    k_conv23<<<NPIX / 2, 256>>>(w3, b3, g2, be2, 2, 1);  // BN2; in B -> out A
    k_conv4 <<<NPIX / 4, 512>>>(w4, b4, g3, be3);        // BN3; in A -> wraw
    k_final<<<NPIX, 128>>>(g4, be4);
    k_max<<<64, 256>>>();
    k_sub<<<NPIX / 256, 256>>>(out);
}

// round 5
// speedup vs baseline: 1.6505x; 1.0781x over previous
#include <cuda_runtime.h>
#include <math.h>
#include <math_constants.h>

#define NPIX  32768      // 128*256 pixels
#define NE    128
#define NS    2048
#define NTOT  (16*128*2048)
#define CNT   4194304.0  // per-channel BN count = NPIX*NE

typedef unsigned long long u64;

// float2-index skew: stride-8 thread bases -> stride 9 (conflict-free wavefronts)
#define XA0(c) ((c) + ((c) >> 3))

// ---------------- scratch ----------------
__device__ float    g_act0[NPIX * 2 * NE];
__device__ float    g_actA[NPIX * 8 * NE];
__device__ float    g_actB[NPIX * 8 * NE];
__device__ float    g_wraw[NPIX * NE];
__device__ float    g_sumI[NPIX];
__device__ float    g_sumQ[NPIX];
__device__ float    g_ydb [NPIX];
__device__ unsigned g_maxsq;
__device__ unsigned g_maxydb;
__device__ double   g_stats[4][16];   // per-layer [sum(8) | sumsq(8)]

__device__ __forceinline__ unsigned ford(float f) {
    unsigned u = __float_as_uint(f);
    return (u & 0x80000000u) ? ~u : (u | 0x80000000u);
}

// packed fp32x2 helpers (lanes = two pixels)
__device__ __forceinline__ u64 ffma2(u64 a, u64 b, u64 c) {
    u64 d;
    asm("fma.rn.f32x2 %0,%1,%2,%3;" : "=l"(d) : "l"(a), "l"(b), "l"(c));
    return d;
}
__device__ __forceinline__ u64 pack2(float lo, float hi) {
    u64 d;
    asm("mov.b64 %0,{%1,%2};" : "=l"(d) : "f"(lo), "f"(hi));
    return d;
}
__device__ __forceinline__ void unpack2(u64 a, float& lo, float& hi) {
    asm("mov.b64 {%0,%1},%2;" : "=f"(lo), "=f"(hi) : "l"(a));
}

__global__ void k_init() {
    int t = threadIdx.x;
    if (t < 64) ((double*)g_stats)[t] = 0.0;
    if (t == 64) g_maxsq = 0u;
    if (t == 65) g_maxydb = 0u;
}

__global__ void k_nrm(const float* __restrict__ id, const float* __restrict__ qd) {
    float m = 0.f;
    for (int i = blockIdx.x * blockDim.x + threadIdx.x; i < NTOT; i += gridDim.x * blockDim.x) {
        float a = id[i], b = qd[i];
        m = fmaxf(m, a * a + b * b);
    }
    for (int off = 16; off; off >>= 1) m = fmaxf(m, __shfl_down_sync(0xffffffffu, m, off));
    __shared__ float sm[8];
    int lane = threadIdx.x & 31, w = threadIdx.x >> 5;
    if (lane == 0) sm[w] = m;
    __syncthreads();
    if (threadIdx.x == 0) {
        float mm = sm[0];
        for (int i = 1; i < (int)(blockDim.x >> 5); i++) mm = fmaxf(mm, sm[i]);
        atomicMax(&g_maxsq, __float_as_uint(mm));
    }
}

__global__ void k_bf(const float* __restrict__ idata, const float* __restrict__ qdata,
                     const float* __restrict__ angles, const float* __restrict__ ele_pos,
                     const float* __restrict__ time_zero, const float* __restrict__ grid) {
    int p = blockIdx.x;
    int e = threadIdx.x;
    float x = grid[p * 3 + 0];
    float z = grid[p * 3 + 2];
    float ang = angles[0];
    float sA, cA;
    sincosf(ang, &sA, &cA);
    float ex  = ele_pos[e * 3];
    float ex0 = ele_pos[0];
    float exL = ele_pos[(NE - 1) * 3];

    const float FSC = (float)(20832000.0 / 1540.0);
    float txdel = (x * sA + z * cA + time_zero[0] * 1540.0f) * FSC;
    float vx = x - ex;
    float dist = sqrtf(vx * vx + z * z);
    float delays = txdel + dist * FSC;
    float d0 = floorf(delays);
    float frac = delays - d0;
    int i0 = (int)d0;

    const float* is = idata + e * NS;
    const float* qs = qdata + e * NS;
    float iv0 = (i0 >= 0 && i0 < NS)         ? is[i0]     : 0.f;
    float iv1 = (i0 + 1 >= 0 && i0 + 1 < NS) ? is[i0 + 1] : 0.f;
    float qv0 = (i0 >= 0 && i0 < NS)         ? qs[i0]     : 0.f;
    float qv1 = (i0 + 1 >= 0 && i0 + 1 < NS) ? qs[i0 + 1] : 0.f;

    float invn = rsqrtf(__uint_as_float(g_maxsq));
    float ifoc = (iv0 * (1.f - frac) + iv1 * frac) * invn;
    float qfoc = (qv0 * (1.f - frac) + qv1 * frac) * invn;

    float tshift = delays / 20832000.0f - (z * 2.0f) / 1540.0f;
    float theta = (float)(2.0 * CUDART_PI * 5208000.0) * tshift;
    float st, ct;
    sincosf(theta, &st, &ct);
    float ir = ifoc * ct - qfoc * st;
    float qr = qfoc * ct + ifoc * st;

    float avx = fabsf(vx);
    bool mrx = (fabsf(z) > avx) || (avx <= 0.001f) ||
               ((vx >= 0.001f)  && (x <= ex0)) ||
               ((vx <= -0.001f) && (x >= exL));
    float xp = x - z * tanf(ang);
    bool mtx = (xp >= ex0 * 1.2f) && (xp <= exL * 1.2f);
    if (!(mrx && mtx)) { ir = 0.f; qr = 0.f; }

    g_act0[p * 256 + e]       = ir;
    g_act0[p * 256 + 128 + e] = qr;

    float si = ir, sq = qr;
    for (int off = 16; off; off >>= 1) {
        si += __shfl_down_sync(0xffffffffu, si, off);
        sq += __shfl_down_sync(0xffffffffu, sq, off);
    }
    __shared__ float sI[4], sQ[4];
    int lane = e & 31, w = e >> 5;
    if (lane == 0) { sI[w] = si; sQ[w] = sq; }
    __syncthreads();
    if (e == 0) {
        g_sumI[p] = sI[0] + sI[1] + sI[2] + sI[3];
        g_sumQ[p] = sQ[0] + sQ[1] + sQ[2] + sQ[3];
    }
}

// ============ conv1: 2->8, K=65, pad=32; dual-pixel f32x2, rolling window ============
__global__ void __launch_bounds__(256, 3) k_conv1(const float* __restrict__ w,
                                                  const float* __restrict__ b) {
    __shared__ float2 swd[1040];        // weights duplicated (w,w), [co][ci][k]
    __shared__ float2 sxp[2][2][220];   // (p0,p1) pairs, skewed; XA0(191)=214
    __shared__ float  sred[16];
    int tid = threadIdx.x;
    int pbase = blockIdx.x * 4;

    for (int i = tid; i < 1040; i += 256) { float v = w[i]; swd[i] = make_float2(v, v); }
    if (tid < 16) sred[tid] = 0.f;
    for (int i = tid; i < 2 * 2 * 192; i += 256) {
        int pp = i / 384, r = i % 384, c = r / 192, x = r % 192;
        int e = x - 32;
        int p0 = pbase + pp * 2;
        float v0 = 0.f, v1 = 0.f;
        if (e >= 0 && e < 128) {
            v0 = g_act0[p0 * 256 + c * 128 + e];
            v1 = g_act0[(p0 + 1) * 256 + c * 128 + e];
        }
        sxp[pp][c][XA0(x)] = make_float2(v0, v1);
    }
    __syncthreads();

    int pp = tid >> 7, t = tid & 127, co = t >> 4, g = t & 15;  // e0 = 8g
    float bias = b[co];
    u64 acc[8];
#pragma unroll
    for (int j = 0; j < 8; j++) acc[j] = pack2(bias, bias);

#pragma unroll
    for (int ci = 0; ci < 2; ci++) {
        const u64* wp  = (const u64*)&swd[(co * 2 + ci) * 65];
        const u64* spg = ((const u64*)&sxp[pp][ci][0]) + 9 * g;  // XA(e0)=9g
        u64 pe[15];
#pragma unroll
        for (int i = 0; i < 15; i++) pe[i] = spg[XA0(i)];
#pragma unroll
        for (int kb = 0; kb < 64; kb += 8) {
#pragma unroll
            for (int k = 0; k < 8; k++) {
                u64 wk = wp[kb + k];
#pragma unroll
                for (int j = 0; j < 8; j++) acc[j] = ffma2(wk, pe[k + j], acc[j]);
            }
#pragma unroll
            for (int i = 0; i < 7; i++) pe[i] = pe[i + 8];
            if (kb < 56) {
#pragma unroll
                for (int i = 7; i < 15; i++) pe[i] = spg[XA0(kb + 8 + i)];
            } else {
                pe[7] = spg[XA0(71)];
            }
        }
        u64 wl = wp[64];
#pragma unroll
        for (int j = 0; j < 8; j++) acc[j] = ffma2(wl, pe[j], acc[j]);
    }

    int p0 = pbase + pp * 2;
    float f0[8], f1[8];
    float s = 0.f, ss = 0.f;
#pragma unroll
    for (int j = 0; j < 8; j++) {
        unpack2(acc[j], f0[j], f1[j]);
        s += f0[j] + f1[j];
        ss += f0[j] * f0[j] + f1[j] * f1[j];
    }
    float2* o0 = (float2*)&g_actA[p0 * 1024 + co * 128 + g * 8];
    float2* o1 = (float2*)&g_actA[(p0 + 1) * 1024 + co * 128 + g * 8];
#pragma unroll
    for (int m = 0; m < 4; m++) {
        o0[m] = make_float2(f0[2 * m], f0[2 * m + 1]);
        o1[m] = make_float2(f1[2 * m], f1[2 * m + 1]);
    }
    for (int off = 8; off; off >>= 1) {
        s  += __shfl_down_sync(0xffffffffu, s,  off, 16);
        ss += __shfl_down_sync(0xffffffffu, ss, off, 16);
    }
    if (g == 0) { atomicAdd(&sred[co], s); atomicAdd(&sred[8 + co], ss); }
    __syncthreads();
    if (tid < 8) {
        atomicAdd(&g_stats[0][tid],     (double)sred[tid]);
        atomicAdd(&g_stats[0][8 + tid], (double)sred[8 + tid]);
    }
}

// ============ conv2/3: BN(prev)+relu on load; 8->8, K=15; dual-pixel f32x2 ============
__global__ void __launch_bounds__(256, 3) k_conv23(const float* __restrict__ w,
                                                   const float* __restrict__ b,
                                                   const float* __restrict__ gam,
                                                   const float* __restrict__ bet,
                                                   int layer, int flip) {
    __shared__ float2 swd[960];         // duplicated weights [co][ci][k]
    __shared__ float2 sxp[2][8][164];   // (p0,p1) pairs, skewed; XA0(141)=158
    __shared__ float  ssc[8], ssh[8];
    __shared__ float  sred[16];
    const float* in  = flip ? g_actB : g_actA;
    float*       out = flip ? g_actA : g_actB;

    int tid = threadIdx.x;
    int pbase = blockIdx.x * 4;

    for (int i = tid; i < 960; i += 256) { float v = w[i]; swd[i] = make_float2(v, v); }
    if (tid < 8) {
        double mu  = g_stats[layer - 1][tid] / CNT;
        double var = g_stats[layer - 1][8 + tid] / CNT - mu * mu;
        float sc = (float)((double)gam[tid] / sqrt(var + 1e-5));
        ssc[tid] = sc;
        ssh[tid] = bet[tid] - (float)mu * sc;
    }
    if (tid < 16) sred[tid] = 0.f;
    __syncthreads();

    for (int i = tid; i < 2 * 8 * 142; i += 256) {
        int pp = i / 1136, r = i % 1136, c = r / 142, x = r % 142;
        int e = x - 7;
        int p0 = pbase + pp * 2;
        float v0 = 0.f, v1 = 0.f;
        if (e >= 0 && e < 128) {
            v0 = fmaxf(fmaf(in[p0 * 1024 + c * 128 + e],       ssc[c], ssh[c]), 0.f);
            v1 = fmaxf(fmaf(in[(p0 + 1) * 1024 + c * 128 + e], ssc[c], ssh[c]), 0.f);
        }
        sxp[pp][c][XA0(x)] = make_float2(v0, v1);
    }
    __syncthreads();

    int pp = tid >> 7, t = tid & 127, co = t >> 4, g = t & 15;
    float bias = b[co];
    u64 acc[8];
#pragma unroll
    for (int j = 0; j < 8; j++) acc[j] = pack2(bias, bias);

#pragma unroll
    for (int ci = 0; ci < 8; ci++) {
        const u64* wp  = (const u64*)&swd[(co * 8 + ci) * 15];
        const u64* spg = ((const u64*)&sxp[pp][ci][0]) + 9 * g;
        u64 pe[15];
#pragma unroll
        for (int i = 0; i < 15; i++) pe[i] = spg[XA0(i)];
#pragma unroll
        for (int k = 0; k < 8; k++) {
            u64 wk = wp[k];
#pragma unroll
            for (int j = 0; j < 8; j++) acc[j] = ffma2(wk, pe[k + j], acc[j]);
        }
#pragma unroll
        for (int i = 0; i < 7; i++) pe[i] = pe[i + 8];
#pragma unroll
        for (int i = 7; i < 14; i++) pe[i] = spg[XA0(i + 8)];  // x=e0+15..e0+21
#pragma unroll
        for (int k = 8; k < 15; k++) {
            u64 wk = wp[k];
#pragma unroll
            for (int j = 0; j < 8; j++) acc[j] = ffma2(wk, pe[k - 8 + j], acc[j]);
        }
    }

    int p0 = pbase + pp * 2;
    float f0[8], f1[8];
    float s = 0.f, ss = 0.f;
#pragma unroll
    for (int j = 0; j < 8; j++) {
        unpack2(acc[j], f0[j], f1[j]);
        s += f0[j] + f1[j];
        ss += f0[j] * f0[j] + f1[j] * f1[j];
    }
    float2* o0 = (float2*)&out[p0 * 1024 + co * 128 + g * 8];
    float2* o1 = (float2*)&out[(p0 + 1) * 1024 + co * 128 + g * 8];
#pragma unroll
    for (int m = 0; m < 4; m++) {
        o0[m] = make_float2(f0[2 * m], f0[2 * m + 1]);
        o1[m] = make_float2(f1[2 * m], f1[2 * m + 1]);
    }
    for (int off = 8; off; off >>= 1) {
        s  += __shfl_down_sync(0xffffffffu, s,  off, 16);
        ss += __shfl_down_sync(0xffffffffu, ss, off, 16);
    }
    if (g == 0) { atomicAdd(&sred[co], s); atomicAdd(&sred[8 + co], ss); }
    __syncthreads();
    if (tid < 8) {
        atomicAdd(&g_stats[layer][tid],     (double)sred[tid]);
        atomicAdd(&g_stats[layer][8 + tid], (double)sred[8 + tid]);
    }
}

// ---- conv4: BN3+relu fused; 8->1, K=3, pad=1 ----
__global__ void __launch_bounds__(512) k_conv4(const float* __restrict__ w,
                                               const float* __restrict__ b,
                                               const float* __restrict__ gam,
                                               const float* __restrict__ bet) {
    __shared__ float sw[24];
    __shared__ float ssc[8], ssh[8];
    __shared__ float sx[4][8][130];
    __shared__ float sred[32];
    int tid = threadIdx.x;
    int pbase = blockIdx.x * 4;

    if (tid < 24) sw[tid] = w[tid];
    if (tid < 8) {
        double mu  = g_stats[2][tid] / CNT;
        double var = g_stats[2][8 + tid] / CNT - mu * mu;
        float sc = (float)((double)gam[tid] / sqrt(var + 1e-5));
        ssc[tid] = sc;
        ssh[tid] = bet[tid] - (float)mu * sc;
    }
    __syncthreads();

    for (int i = tid; i < 4 * 8 * 130; i += 512) {
        int lp = i / 1040, r = i % 1040, c = r / 130, xi = r % 130;
        int e = xi - 1;
        float v = 0.f;
        if (e >= 0 && e < 128)
            v = fmaxf(fmaf(g_actA[(pbase + lp) * 1024 + c * 128 + e], ssc[c], ssh[c]), 0.f);
        sx[lp][c][xi] = v;
    }
    __syncthreads();

    int lp = tid >> 7, e = tid & 127;
    float acc = b[0];
#pragma unroll
    for (int ci = 0; ci < 8; ci++)
#pragma unroll
        for (int k = 0; k < 3; k++)
            acc = fmaf(sw[ci * 3 + k], sx[lp][ci][e + k], acc);

    g_wraw[(pbase + lp) * 128 + e] = acc;

    float s = acc, ss = acc * acc;
    for (int off = 16; off; off >>= 1) {
        s  += __shfl_down_sync(0xffffffffu, s,  off);
        ss += __shfl_down_sync(0xffffffffu, ss, off);
    }
    int lane = tid & 31, wix = tid >> 5;
    if (lane == 0) { sred[wix] = s; sred[16 + wix] = ss; }
    __syncthreads();
    if (tid == 0) {
        float S = 0.f, SS = 0.f;
        for (int i = 0; i < 16; i++) { S += sred[i]; SS += sred[16 + i]; }
        atomicAdd(&g_stats[3][0], (double)S);
        atomicAdd(&g_stats[3][1], (double)SS);
    }
}

__global__ void k_final(const float* __restrict__ gam, const float* __restrict__ bet) {
    int p = blockIdx.x;
    int e = threadIdx.x;
    double mu  = g_stats[3][0] / CNT;
    double var = g_stats[3][1] / CNT - mu * mu;
    float sc = (float)((double)gam[0] / sqrt(var + 1e-5));
    float sh = bet[0] - (float)mu * sc;
    float wv = fmaxf(fmaf(g_wraw[p * 128 + e], sc, sh), 0.f);
    for (int off = 16; off; off >>= 1) wv += __shfl_down_sync(0xffffffffu, wv, off);
    __shared__ float sm[4];
    int lane = e & 31, w = e >> 5;
    if (lane == 0) sm[w] = wv;
    __syncthreads();
    if (e == 0) {
        float sW = sm[0] + sm[1] + sm[2] + sm[3];
        float cI = sW * g_sumI[p] * (1.0f / 128.0f);
        float cQ = sW * g_sumQ[p] * (1.0f / 128.0f);
        float mag = sqrtf(cI * cI + cQ * cQ);
        g_ydb[p] = 20.0f * log10f(mag + 1e-20f);
    }
}

__global__ void k_max() {
    float m = -CUDART_INF_F;
    for (int i = blockIdx.x * blockDim.x + threadIdx.x; i < NPIX; i += gridDim.x * blockDim.x)
        m = fmaxf(m, g_ydb[i]);
    for (int off = 16; off; off >>= 1) m = fmaxf(m, __shfl_down_sync(0xffffffffu, m, off));
    __shared__ float sm[8];
    int lane = threadIdx.x & 31, w = threadIdx.x >> 5;
    if (lane == 0) sm[w] = m;
    __syncthreads();
    if (threadIdx.x == 0) {
        float mm = sm[0];
        for (int i = 1; i < (int)(blockDim.x >> 5); i++) mm = fmaxf(mm, sm[i]);
        atomicMax(&g_maxydb, ford(mm));
    }
}

__global__ void k_sub(float* __restrict__ out) {
    int i = blockIdx.x * blockDim.x + threadIdx.x;
    unsigned u = g_maxydb;
    float mx = (u & 0x80000000u) ? __uint_as_float(u & 0x7fffffffu) : __uint_as_float(~u);
    if (i < NPIX) out[i] = g_ydb[i] - mx;
}

extern "C" void kernel_launch(void* const* d_in, const int* in_sizes, int n_in,
                              void* d_out, int out_size) {
    const float* idata     = (const float*)d_in[0];
    const float* qdata     = (const float*)d_in[1];
    const float* angles    = (const float*)d_in[2];
    const float* ele_pos   = (const float*)d_in[3];
    const float* time_zero = (const float*)d_in[4];
    const float* grid      = (const float*)d_in[5];
    const float* w1 = (const float*)d_in[6],  *b1 = (const float*)d_in[7];
    const float* g1 = (const float*)d_in[8],  *be1 = (const float*)d_in[9];
    const float* w2 = (const float*)d_in[10], *b2 = (const float*)d_in[11];
    const float* g2 = (const float*)d_in[12], *be2 = (const float*)d_in[13];
    const float* w3 = (const float*)d_in[14], *b3 = (const float*)d_in[15];
    const float* g3 = (const float*)d_in[16], *be3 = (const float*)d_in[17];
    const float* w4 = (const float*)d_in[18], *b4 = (const float*)d_in[19];
    const float* g4 = (const float*)d_in[20], *be4 = (const float*)d_in[21];
    float* out = (float*)d_out;

    k_init<<<1, 128>>>();
    k_nrm<<<1024, 256>>>(idata, qdata);
    k_bf<<<NPIX, 128>>>(idata, qdata, angles, ele_pos, time_zero, grid);
    k_conv1<<<NPIX / 4, 256>>>(w1, b1);
    k_conv23<<<NPIX / 4, 256>>>(w2, b2, g1, be1, 1, 0);  // BN1; in A -> out B
    k_conv23<<<NPIX / 4, 256>>>(w3, b3, g2, be2, 2, 1);  // BN2; in B -> out A
    k_conv4 <<<NPIX / 4, 512>>>(w4, b4, g3, be3);        // BN3; in A -> wraw
    k_final<<<NPIX, 128>>>(g4, be4);
    k_max<<<64, 256>>>();
    k_sub<<<NPIX / 256, 256>>>(out);
}

// round 6
// speedup vs baseline: 1.9020x; 1.1524x over previous
#include <cuda_runtime.h>
#include <math.h>
#include <math_constants.h>

#define NPIX  32768      // 128*256 pixels
#define NE    128
#define NS    2048
#define NTOT  (16*128*2048)
#define CNT   4194304.0  // per-channel BN count = NPIX*NE

typedef unsigned long long u64;

// float2-index skew: stride-8 thread bases -> stride 9 (conflict-free wavefronts)
#define XA0(c) ((c) + ((c) >> 3))

// ---------------- scratch ----------------
__device__ float    g_act0[NPIX * 2 * NE];
__device__ float    g_actA[NPIX * 8 * NE];
__device__ float    g_actB[NPIX * 8 * NE];
__device__ float    g_wraw[NPIX * NE];
__device__ float    g_sumI[NPIX];
__device__ float    g_sumQ[NPIX];
__device__ float    g_ydb [NPIX];
__device__ unsigned g_maxsq;
__device__ unsigned g_maxydb;
__device__ double   g_stats[4][16];   // per-layer [sum(8) | sumsq(8)]

__device__ __forceinline__ unsigned ford(float f) {
    unsigned u = __float_as_uint(f);
    return (u & 0x80000000u) ? ~u : (u | 0x80000000u);
}

// packed fp32x2 helpers (lanes = two pixels)
__device__ __forceinline__ u64 ffma2(u64 a, u64 b, u64 c) {
    u64 d;
    asm("fma.rn.f32x2 %0,%1,%2,%3;" : "=l"(d) : "l"(a), "l"(b), "l"(c));
    return d;
}
__device__ __forceinline__ u64 pack2(float lo, float hi) {
    u64 d;
    asm("mov.b64 %0,{%1,%2};" : "=l"(d) : "f"(lo), "f"(hi));
    return d;
}
__device__ __forceinline__ void unpack2(u64 a, float& lo, float& hi) {
    asm("mov.b64 {%0,%1},%2;" : "=f"(lo), "=f"(hi) : "l"(a));
}

__global__ void k_init() {
    int t = threadIdx.x;
    if (t < 64) ((double*)g_stats)[t] = 0.0;
    if (t == 64) g_maxsq = 0u;
    if (t == 65) g_maxydb = 0u;
}

__global__ void k_nrm(const float* __restrict__ id, const float* __restrict__ qd) {
    float m = 0.f;
    for (int i = blockIdx.x * blockDim.x + threadIdx.x; i < NTOT; i += gridDim.x * blockDim.x) {
        float a = id[i], b = qd[i];
        m = fmaxf(m, a * a + b * b);
    }
    for (int off = 16; off; off >>= 1) m = fmaxf(m, __shfl_down_sync(0xffffffffu, m, off));
    __shared__ float sm[8];
    int lane = threadIdx.x & 31, w = threadIdx.x >> 5;
    if (lane == 0) sm[w] = m;
    __syncthreads();
    if (threadIdx.x == 0) {
        float mm = sm[0];
        for (int i = 1; i < (int)(blockDim.x >> 5); i++) mm = fmaxf(mm, sm[i]);
        atomicMax(&g_maxsq, __float_as_uint(mm));
    }
}

__global__ void k_bf(const float* __restrict__ idata, const float* __restrict__ qdata,
                     const float* __restrict__ angles, const float* __restrict__ ele_pos,
                     const float* __restrict__ time_zero, const float* __restrict__ grid) {
    int p = blockIdx.x;
    int e = threadIdx.x;
    float x = grid[p * 3 + 0];
    float z = grid[p * 3 + 2];
    float ang = angles[0];
    float sA, cA;
    sincosf(ang, &sA, &cA);
    float ex  = ele_pos[e * 3];
    float ex0 = ele_pos[0];
    float exL = ele_pos[(NE - 1) * 3];

    const float FSC = (float)(20832000.0 / 1540.0);
    float txdel = (x * sA + z * cA + time_zero[0] * 1540.0f) * FSC;
    float vx = x - ex;
    float dist = sqrtf(vx * vx + z * z);
    float delays = txdel + dist * FSC;
    float d0 = floorf(delays);
    float frac = delays - d0;
    int i0 = (int)d0;

    const float* is = idata + e * NS;
    const float* qs = qdata + e * NS;
    float iv0 = (i0 >= 0 && i0 < NS)         ? is[i0]     : 0.f;
    float iv1 = (i0 + 1 >= 0 && i0 + 1 < NS) ? is[i0 + 1] : 0.f;
    float qv0 = (i0 >= 0 && i0 < NS)         ? qs[i0]     : 0.f;
    float qv1 = (i0 + 1 >= 0 && i0 + 1 < NS) ? qs[i0 + 1] : 0.f;

    float invn = rsqrtf(__uint_as_float(g_maxsq));
    float ifoc = (iv0 * (1.f - frac) + iv1 * frac) * invn;
    float qfoc = (qv0 * (1.f - frac) + qv1 * frac) * invn;

    float tshift = delays / 20832000.0f - (z * 2.0f) / 1540.0f;
    float theta = (float)(2.0 * CUDART_PI * 5208000.0) * tshift;
    float st, ct;
    sincosf(theta, &st, &ct);
    float ir = ifoc * ct - qfoc * st;
    float qr = qfoc * ct + ifoc * st;

    float avx = fabsf(vx);
    bool mrx = (fabsf(z) > avx) || (avx <= 0.001f) ||
               ((vx >= 0.001f)  && (x <= ex0)) ||
               ((vx <= -0.001f) && (x >= exL));
    float xp = x - z * tanf(ang);
    bool mtx = (xp >= ex0 * 1.2f) && (xp <= exL * 1.2f);
    if (!(mrx && mtx)) { ir = 0.f; qr = 0.f; }

    g_act0[p * 256 + e]       = ir;
    g_act0[p * 256 + 128 + e] = qr;

    float si = ir, sq = qr;
    for (int off = 16; off; off >>= 1) {
        si += __shfl_down_sync(0xffffffffu, si, off);
        sq += __shfl_down_sync(0xffffffffu, sq, off);
    }
    __shared__ float sI[4], sQ[4];
    int lane = e & 31, w = e >> 5;
    if (lane == 0) { sI[w] = si; sQ[w] = sq; }
    __syncthreads();
    if (e == 0) {
        g_sumI[p] = sI[0] + sI[1] + sI[2] + sI[3];
        g_sumQ[p] = sQ[0] + sQ[1] + sQ[2] + sQ[3];
    }
}

// ============ conv1: 2->8, K=65, pad=32; dual-pixel f32x2, rolling window ============
__global__ void __launch_bounds__(256, 4) k_conv1(const float* __restrict__ w,
                                                  const float* __restrict__ b) {
    __shared__ float2 swd[1040];        // weights duplicated (w,w), [co][ci][k]
    __shared__ float2 sxp[2][2][220];   // (p0,p1) pairs, skewed; XA0(191)=214
    __shared__ float  sred[16];
    int tid = threadIdx.x;
    int pbase = blockIdx.x * 4;

    for (int i = tid; i < 1040; i += 256) { float v = w[i]; swd[i] = make_float2(v, v); }
    if (tid < 16) sred[tid] = 0.f;
    for (int i = tid; i < 2 * 2 * 192; i += 256) {
        int pp = i / 384, r = i % 384, c = r / 192, x = r % 192;
        int e = x - 32;
        int p0 = pbase + pp * 2;
        float v0 = 0.f, v1 = 0.f;
        if (e >= 0 && e < 128) {
            v0 = g_act0[p0 * 256 + c * 128 + e];
            v1 = g_act0[(p0 + 1) * 256 + c * 128 + e];
        }
        sxp[pp][c][XA0(x)] = make_float2(v0, v1);
    }
    __syncthreads();

    int pp = tid >> 7, t = tid & 127, co = t >> 4, g = t & 15;  // e0 = 8g
    float bias = b[co];
    u64 acc[8];
#pragma unroll
    for (int j = 0; j < 8; j++) acc[j] = pack2(bias, bias);

#pragma unroll
    for (int ci = 0; ci < 2; ci++) {
        const u64* wp  = (const u64*)&swd[(co * 2 + ci) * 65];
        const u64* spg = ((const u64*)&sxp[pp][ci][0]) + 9 * g;  // XA(e0)=9g
        u64 pe[15];
#pragma unroll
        for (int i = 0; i < 15; i++) pe[i] = spg[XA0(i)];
#pragma unroll
        for (int kb = 0; kb < 64; kb += 8) {
#pragma unroll
            for (int k = 0; k < 8; k++) {
                u64 wk = wp[kb + k];
#pragma unroll
                for (int j = 0; j < 8; j++) acc[j] = ffma2(wk, pe[k + j], acc[j]);
            }
#pragma unroll
            for (int i = 0; i < 7; i++) pe[i] = pe[i + 8];
            if (kb < 56) {
#pragma unroll
                for (int i = 7; i < 15; i++) pe[i] = spg[XA0(kb + 8 + i)];
            } else {
                pe[7] = spg[XA0(71)];
            }
        }
        u64 wl = wp[64];
#pragma unroll
        for (int j = 0; j < 8; j++) acc[j] = ffma2(wl, pe[j], acc[j]);
    }

    int p0 = pbase + pp * 2;
    float f0[8], f1[8];
    float s = 0.f, ss = 0.f;
#pragma unroll
    for (int j = 0; j < 8; j++) {
        unpack2(acc[j], f0[j], f1[j]);
        s += f0[j] + f1[j];
        ss += f0[j] * f0[j] + f1[j] * f1[j];
    }
    float4* o0 = (float4*)&g_actA[p0 * 1024 + co * 128 + g * 8];
    float4* o1 = (float4*)&g_actA[(p0 + 1) * 1024 + co * 128 + g * 8];
    o0[0] = make_float4(f0[0], f0[1], f0[2], f0[3]);
    o0[1] = make_float4(f0[4], f0[5], f0[6], f0[7]);
    o1[0] = make_float4(f1[0], f1[1], f1[2], f1[3]);
    o1[1] = make_float4(f1[4], f1[5], f1[6], f1[7]);
    for (int off = 8; off; off >>= 1) {
        s  += __shfl_down_sync(0xffffffffu, s,  off, 16);
        ss += __shfl_down_sync(0xffffffffu, ss, off, 16);
    }
    if (g == 0) { atomicAdd(&sred[co], s); atomicAdd(&sred[8 + co], ss); }
    __syncthreads();
    if (tid < 8) {
        atomicAdd(&g_stats[0][tid],     (double)sred[tid]);
        atomicAdd(&g_stats[0][8 + tid], (double)sred[8 + tid]);
    }
}

// ============ conv2/3: BN(prev)+relu on load; 8->8, K=15; dual-pixel f32x2 ============
__global__ void __launch_bounds__(256, 4) k_conv23(const float* __restrict__ w,
                                                   const float* __restrict__ b,
                                                   const float* __restrict__ gam,
                                                   const float* __restrict__ bet,
                                                   int layer, int flip) {
    __shared__ float2 swd[960];         // duplicated weights [co][ci][k]
    __shared__ float2 sxp[2][8][164];   // (p0,p1) pairs, skewed; XA0(141)=158
    __shared__ float  ssc[8], ssh[8];
    __shared__ float  sred[16];
    const float* in  = flip ? g_actB : g_actA;
    float*       out = flip ? g_actA : g_actB;

    int tid = threadIdx.x;
    int pbase = blockIdx.x * 4;

    for (int i = tid; i < 960; i += 256) { float v = w[i]; swd[i] = make_float2(v, v); }
    if (tid < 8) {
        double mu  = g_stats[layer - 1][tid] / CNT;
        double var = g_stats[layer - 1][8 + tid] / CNT - mu * mu;
        float sc = (float)((double)gam[tid] / sqrt(var + 1e-5));
        ssc[tid] = sc;
        ssh[tid] = bet[tid] - (float)mu * sc;
    }
    if (tid < 16) sred[tid] = 0.f;
    __syncthreads();

    for (int i = tid; i < 2 * 8 * 142; i += 256) {
        int pp = i / 1136, r = i % 1136, c = r / 142, x = r % 142;
        int e = x - 7;
        int p0 = pbase + pp * 2;
        float v0 = 0.f, v1 = 0.f;
        if (e >= 0 && e < 128) {
            v0 = fmaxf(fmaf(in[p0 * 1024 + c * 128 + e],       ssc[c], ssh[c]), 0.f);
            v1 = fmaxf(fmaf(in[(p0 + 1) * 1024 + c * 128 + e], ssc[c], ssh[c]), 0.f);
        }
        sxp[pp][c][XA0(x)] = make_float2(v0, v1);
    }
    __syncthreads();

    int pp = tid >> 7, t = tid & 127, co = t >> 4, g = t & 15;
    float bias = b[co];
    u64 acc[8];
#pragma unroll
    for (int j = 0; j < 8; j++) acc[j] = pack2(bias, bias);

#pragma unroll
    for (int ci = 0; ci < 8; ci++) {
        const u64* wp  = (const u64*)&swd[(co * 8 + ci) * 15];
        const u64* spg = ((const u64*)&sxp[pp][ci][0]) + 9 * g;
        u64 pe[15];
#pragma unroll
        for (int i = 0; i < 15; i++) pe[i] = spg[XA0(i)];
#pragma unroll
        for (int k = 0; k < 8; k++) {
            u64 wk = wp[k];
#pragma unroll
            for (int j = 0; j < 8; j++) acc[j] = ffma2(wk, pe[k + j], acc[j]);
        }
#pragma unroll
        for (int i = 0; i < 7; i++) pe[i] = pe[i + 8];
#pragma unroll
        for (int i = 7; i < 14; i++) pe[i] = spg[XA0(i + 8)];  // x=e0+15..e0+21
#pragma unroll
        for (int k = 8; k < 15; k++) {
            u64 wk = wp[k];
#pragma unroll
            for (int j = 0; j < 8; j++) acc[j] = ffma2(wk, pe[k - 8 + j], acc[j]);
        }
    }

    int p0 = pbase + pp * 2;
    float f0[8], f1[8];
    float s = 0.f, ss = 0.f;
#pragma unroll
    for (int j = 0; j < 8; j++) {
        unpack2(acc[j], f0[j], f1[j]);
        s += f0[j] + f1[j];
        ss += f0[j] * f0[j] + f1[j] * f1[j];
    }
    float4* o0 = (float4*)&out[p0 * 1024 + co * 128 + g * 8];
    float4* o1 = (float4*)&out[(p0 + 1) * 1024 + co * 128 + g * 8];
    o0[0] = make_float4(f0[0], f0[1], f0[2], f0[3]);
    o0[1] = make_float4(f0[4], f0[5], f0[6], f0[7]);
    o1[0] = make_float4(f1[0], f1[1], f1[2], f1[3]);
    o1[1] = make_float4(f1[4], f1[5], f1[6], f1[7]);
    for (int off = 8; off; off >>= 1) {
        s  += __shfl_down_sync(0xffffffffu, s,  off, 16);
        ss += __shfl_down_sync(0xffffffffu, ss, off, 16);
    }
    if (g == 0) { atomicAdd(&sred[co], s); atomicAdd(&sred[8 + co], ss); }
    __syncthreads();
    if (tid < 8) {
        atomicAdd(&g_stats[layer][tid],     (double)sred[tid]);
        atomicAdd(&g_stats[layer][8 + tid], (double)sred[8 + tid]);
    }
}

// ---- conv4: BN3+relu fused; 8->1, K=3, pad=1 ----
__global__ void __launch_bounds__(512) k_conv4(const float* __restrict__ w,
                                               const float* __restrict__ b,
                                               const float* __restrict__ gam,
                                               const float* __restrict__ bet) {
    __shared__ float sw[24];
    __shared__ float ssc[8], ssh[8];
    __shared__ float sx[4][8][130];
    __shared__ float sred[32];
    int tid = threadIdx.x;
    int pbase = blockIdx.x * 4;

    if (tid < 24) sw[tid] = w[tid];
    if (tid < 8) {
        double mu  = g_stats[2][tid] / CNT;
        double var = g_stats[2][8 + tid] / CNT - mu * mu;
        float sc = (float)((double)gam[tid] / sqrt(var + 1e-5));
        ssc[tid] = sc;
        ssh[tid] = bet[tid] - (float)mu * sc;
    }
    __syncthreads();

    for (int i = tid; i < 4 * 8 * 130; i += 512) {
        int lp = i / 1040, r = i % 1040, c = r / 130, xi = r % 130;
        int e = xi - 1;
        float v = 0.f;
        if (e >= 0 && e < 128)
            v = fmaxf(fmaf(g_actA[(pbase + lp) * 1024 + c * 128 + e], ssc[c], ssh[c]), 0.f);
        sx[lp][c][xi] = v;
    }
    __syncthreads();

    int lp = tid >> 7, e = tid & 127;
    float acc = b[0];
#pragma unroll
    for (int ci = 0; ci < 8; ci++)
#pragma unroll
        for (int k = 0; k < 3; k++)
            acc = fmaf(sw[ci * 3 + k], sx[lp][ci][e + k], acc);

    g_wraw[(pbase + lp) * 128 + e] = acc;

    float s = acc, ss = acc * acc;
    for (int off = 16; off; off >>= 1) {
        s  += __shfl_down_sync(0xffffffffu, s,  off);
        ss += __shfl_down_sync(0xffffffffu, ss, off);
    }
    int lane = tid & 31, wix = tid >> 5;
    if (lane == 0) { sred[wix] = s; sred[16 + wix] = ss; }
    __syncthreads();
    if (tid == 0) {
        float S = 0.f, SS = 0.f;
        for (int i = 0; i < 16; i++) { S += sred[i]; SS += sred[16 + i]; }
        atomicAdd(&g_stats[3][0], (double)S);
        atomicAdd(&g_stats[3][1], (double)SS);
    }
}

__global__ void k_final(const float* __restrict__ gam, const float* __restrict__ bet) {
    int p = blockIdx.x;
    int e = threadIdx.x;
    double mu  = g_stats[3][0] / CNT;
    double var = g_stats[3][1] / CNT - mu * mu;
    float sc = (float)((double)gam[0] / sqrt(var + 1e-5));
    float sh = bet[0] - (float)mu * sc;
    float wv = fmaxf(fmaf(g_wraw[p * 128 + e], sc, sh), 0.f);
    for (int off = 16; off; off >>= 1) wv += __shfl_down_sync(0xffffffffu, wv, off);
    __shared__ float sm[4];
    int lane = e & 31, w = e >> 5;
    if (lane == 0) sm[w] = wv;
    __syncthreads();
    if (e == 0) {
        float sW = sm[0] + sm[1] + sm[2] + sm[3];
        float cI = sW * g_sumI[p] * (1.0f / 128.0f);
        float cQ = sW * g_sumQ[p] * (1.0f / 128.0f);
        float mag = sqrtf(cI * cI + cQ * cQ);
        g_ydb[p] = 20.0f * log10f(mag + 1e-20f);
    }
}

__global__ void k_max() {
    float m = -CUDART_INF_F;
    for (int i = blockIdx.x * blockDim.x + threadIdx.x; i < NPIX; i += gridDim.x * blockDim.x)
        m = fmaxf(m, g_ydb[i]);
    for (int off = 16; off; off >>= 1) m = fmaxf(m, __shfl_down_sync(0xffffffffu, m, off));
    __shared__ float sm[8];
    int lane = threadIdx.x & 31, w = threadIdx.x >> 5;
    if (lane == 0) sm[w] = m;
    __syncthreads();
    if (threadIdx.x == 0) {
        float mm = sm[0];
        for (int i = 1; i < (int)(blockDim.x >> 5); i++) mm = fmaxf(mm, sm[i]);
        atomicMax(&g_maxydb, ford(mm));
    }
}

__global__ void k_sub(float* __restrict__ out) {
    int i = blockIdx.x * blockDim.x + threadIdx.x;
    unsigned u = g_maxydb;
    float mx = (u & 0x80000000u) ? __uint_as_float(u & 0x7fffffffu) : __uint_as_float(~u);
    if (i < NPIX) out[i] = g_ydb[i] - mx;
}

extern "C" void kernel_launch(void* const* d_in, const int* in_sizes, int n_in,
                              void* d_out, int out_size) {
    const float* idata     = (const float*)d_in[0];
    const float* qdata     = (const float*)d_in[1];
    const float* angles    = (const float*)d_in[2];
    const float* ele_pos   = (const float*)d_in[3];
    const float* time_zero = (const float*)d_in[4];
    const float* grid      = (const float*)d_in[5];
    const float* w1 = (const float*)d_in[6],  *b1 = (const float*)d_in[7];
    const float* g1 = (const float*)d_in[8],  *be1 = (const float*)d_in[9];
    const float* w2 = (const float*)d_in[10], *b2 = (const float*)d_in[11];
    const float* g2 = (const float*)d_in[12], *be2 = (const float*)d_in[13];
    const float* w3 = (const float*)d_in[14], *b3 = (const float*)d_in[15];
    const float* g3 = (const float*)d_in[16], *be3 = (const float*)d_in[17];
    const float* w4 = (const float*)d_in[18], *b4 = (const float*)d_in[19];
    const float* g4 = (const float*)d_in[20], *be4 = (const float*)d_in[21];
    float* out = (float*)d_out;

    k_init<<<1, 128>>>();
    k_nrm<<<1024, 256>>>(idata, qdata);
    k_bf<<<NPIX, 128>>>(idata, qdata, angles, ele_pos, time_zero, grid);
    k_conv1<<<NPIX / 4, 256>>>(w1, b1);
    k_conv23<<<NPIX / 4, 256>>>(w2, b2, g1, be1, 1, 0);  // BN1; in A -> out B
    k_conv23<<<NPIX / 4, 256>>>(w3, b3, g2, be2, 2, 1);  // BN2; in B -> out A
    k_conv4 <<<NPIX / 4, 512>>>(w4, b4, g3, be3);        // BN3; in A -> wraw
    k_final<<<NPIX, 128>>>(g4, be4);
    k_max<<<64, 256>>>();
    k_sub<<<NPIX / 256, 256>>>(out);
}